// round 11
// baseline (speedup 1.0000x reference)
#include <cuda_runtime.h>
#include <cstdint>

// Problem constants
#define Bb 512
#define Tt 512
#define Ff 32
#define Hh 128
#define Ll 5
#define ROWS 4          // batch rows per CTA
#define K2T 80          // (H+F)/2 total packed k-pairs
#define K2Q 20          // k-pairs per k-quarter (interleaved: k2 = kk*4 + kq)
#define KREG 13         // reg-resident kk per register gate
#define KSM  7          // smem-tail kk per register gate (K2Q - KREG)
#define NTHREADS 512

// ---------------- smem layout ----------------
struct __align__(16) Smem {
    float2 wlo[K2Q][2][128][4];  // 163840 B: gates g0+256, g0+384: [kk][j][g0][kq]
    float2 whi[KSM][2][128][4];  // 57344 B: reg-gates' tail kk (g0, g0+128)
    float2 hx[2][K2T][ROWS];     // 5120 B: double-buffered state; k<64 -> h, k>=64 -> x_t
};
// total 226,304 B (dynamic smem)

// packed f32x2 FMA (Blackwell)
__device__ __forceinline__ unsigned long long ffma2(unsigned long long a,
                                                    unsigned long long b,
                                                    unsigned long long c) {
    unsigned long long d;
    asm("fma.rn.f32x2 %0, %1, %2, %3;" : "=l"(d) : "l"(a), "l"(b), "l"(c));
    return d;
}
__device__ __forceinline__ float hsum2(unsigned long long a) {
    float2 v = *reinterpret_cast<float2*>(&a);
    return v.x + v.y;
}
__device__ __forceinline__ unsigned long long f2bits(float2 v) {
    return *reinterpret_cast<unsigned long long*>(&v);
}
__device__ __forceinline__ float sigf(float v) {
    return __fdividef(1.f, 1.f + __expf(-v));
}
__device__ __forceinline__ float tanh_fast(float v) {
    float a = fabsf(v);
    float e = __expf(-2.f * a);
    float r = __fdividef(1.f - e, 1.f + e);
    return copysignf(r, v);
}

// ---------------- kernel ----------------
// 128 CTAs x 512 threads. CTA b owns batch rows [4b, 4b+4) and all 512 gate rows.
// Thread t: g0 = t>>2 (gates {g0, g0+128, g0+256, g0+384} = i,f,g,o of column g0),
// kq = t&3 (k2 set {kq, kq+4, ..., kq+76}, 20 interleaved k-pairs).
// Gates g0, g0+128: 13 of 20 kk in REGISTERS (52 regs), 7 kk from smem.
// Gates g0+256, g0+384: all 20 kk from smem (conflict-free, warp-contiguous).
// Per step (ONE sync): GEMM 20 iters x (2 broadcast LDS.128 h + 2-4 LDS.64 w +
// 16 FFMA2) -> 16 partials; kq-reduction via 24 SHFL.BFLY in-warp (lane kq keeps
// row kq); c/h update for (row kq, col g0), c in a register; h + x(t+1) written
// into the OTHER hx buffer; sync.
__global__ void __launch_bounds__(NTHREADS, 1)
lstm_kernel(const float* __restrict__ x,
            const float* __restrict__ W_ih,
            const float* __restrict__ W_hh,
            const float* __restrict__ b_ih,
            const float* __restrict__ b_hh,
            const float* __restrict__ W_fc,
            const float* __restrict__ b_fc,
            float* __restrict__ out)
{
    extern __shared__ unsigned char smem_raw[];
    Smem* s = reinterpret_cast<Smem*>(smem_raw);
    const int tid  = threadIdx.x;
    const int g0   = tid >> 2;          // h column / base gate row
    const int kq   = tid & 3;           // k-interleave lane
    const int row0 = blockIdx.x * ROWS;

    // ---- prologue: weights -> regs (g0,g0+128 first 13 kk) and smem ----
    const float2* whh2 = reinterpret_cast<const float2*>(W_hh);   // row g: 64 float2
    const float2* wih2 = reinterpret_cast<const float2*>(W_ih);   // row g: 16 float2
    unsigned long long Wr0[KREG], Wr1[KREG];
    #pragma unroll
    for (int kk = 0; kk < K2Q; ++kk) {
        int k2 = kk * 4 + kq;
        float2 v0 = (k2 < 64) ? __ldg(whh2 + (size_t)g0 * 64 + k2)
                              : __ldg(wih2 + (size_t)g0 * 16 + (k2 - 64));
        float2 v1 = (k2 < 64) ? __ldg(whh2 + (size_t)(g0 + 128) * 64 + k2)
                              : __ldg(wih2 + (size_t)(g0 + 128) * 16 + (k2 - 64));
        if (kk < KREG) {
            Wr0[kk] = f2bits(v0);
            Wr1[kk] = f2bits(v1);
        } else {
            s->whi[kk - KREG][0][g0][kq] = v0;
            s->whi[kk - KREG][1][g0][kq] = v1;
        }
        float2 v2 = (k2 < 64) ? __ldg(whh2 + (size_t)(g0 + 256) * 64 + k2)
                              : __ldg(wih2 + (size_t)(g0 + 256) * 16 + (k2 - 64));
        s->wlo[kk][0][g0][kq] = v2;
        float2 v3 = (k2 < 64) ? __ldg(whh2 + (size_t)(g0 + 384) * 64 + k2)
                              : __ldg(wih2 + (size_t)(g0 + 384) * 16 + (k2 - 64));
        s->wlo[kk][1][g0][kq] = v3;
    }
    const float cb0 = b_ih[g0]       + b_hh[g0];
    const float cb1 = b_ih[g0 + 128] + b_hh[g0 + 128];
    const float cb2 = b_ih[g0 + 256] + b_hh[g0 + 256];
    const float cb3 = b_ih[g0 + 384] + b_hh[g0 + 384];

    // ---- init buf 0: zero h region (k2 0..63), x(t=0) into k2 64..79 ----
    if (tid < 256) s->hx[0][tid >> 2][tid & 3] = make_float2(0.f, 0.f);
    const int xr = (tid >> 5) & 3, xf = tid & 31;          // x-loader role for tid<128
    const float* xptr = x + (size_t)(row0 + xr) * Tt * Ff + xf;
    if (tid < 128) {
        float v = __ldg(xptr);
        reinterpret_cast<float*>(&s->hx[0][64 + (xf >> 1)][xr])[xf & 1] = v;
    }
    __syncthreads();

    const unsigned long long* wlo_p =
        reinterpret_cast<const unsigned long long*>(s->wlo) + (size_t)g0 * 4 + kq;
    const unsigned long long* whi_p =
        reinterpret_cast<const unsigned long long*>(s->whi) + (size_t)g0 * 4 + kq;
    const unsigned long long* hx_u = reinterpret_cast<const unsigned long long*>(s->hx);
    float* hx_f = reinterpret_cast<float*>(s->hx);

    const int p0 = kq & 1;              // row bit0 this lane keeps
    const int p1 = (kq >> 1) & 1;       // row bit1 this lane keeps
    float c_ = 0.f;                     // cell state: row kq, col g0

    for (int st = 0; st < Tt; ++st) {
        // prefetch next x slice (tid<128)
        float xnext = 0.f;
        if (tid < 128 && st + 1 < Tt) xnext = __ldg(xptr + (size_t)(st + 1) * Ff);

        // ---- GEMM: 4 gates x 4 rows over my 20 interleaved k2 ----
        const unsigned long long* hq = hx_u + (size_t)(st & 1) * (K2T * ROWS) + kq * ROWS;
        unsigned long long a0[4], a1[4], a2[4], a3[4];
        #pragma unroll
        for (int r = 0; r < 4; ++r) { a0[r] = 0ull; a1[r] = 0ull; a2[r] = 0ull; a3[r] = 0ull; }
        #pragma unroll
        for (int kk = 0; kk < K2Q; ++kk) {
            ulonglong2 hAB = *reinterpret_cast<const ulonglong2*>(hq + kk * 16);     // rows 0,1
            ulonglong2 hCD = *reinterpret_cast<const ulonglong2*>(hq + kk * 16 + 2); // rows 2,3
            unsigned long long w0 = (kk < KREG) ? Wr0[kk]
                                                : whi_p[(size_t)((kk - KREG) * 2) * 512];
            unsigned long long w1 = (kk < KREG) ? Wr1[kk]
                                                : whi_p[(size_t)((kk - KREG) * 2 + 1) * 512];
            unsigned long long w2 = wlo_p[(size_t)(kk * 2) * 512];
            unsigned long long w3 = wlo_p[(size_t)(kk * 2 + 1) * 512];
            a0[0] = ffma2(hAB.x, w0, a0[0]); a0[1] = ffma2(hAB.y, w0, a0[1]);
            a0[2] = ffma2(hCD.x, w0, a0[2]); a0[3] = ffma2(hCD.y, w0, a0[3]);
            a1[0] = ffma2(hAB.x, w1, a1[0]); a1[1] = ffma2(hAB.y, w1, a1[1]);
            a1[2] = ffma2(hCD.x, w1, a1[2]); a1[3] = ffma2(hCD.y, w1, a1[3]);
            a2[0] = ffma2(hAB.x, w2, a2[0]); a2[1] = ffma2(hAB.y, w2, a2[1]);
            a2[2] = ffma2(hCD.x, w2, a2[2]); a2[3] = ffma2(hCD.y, w2, a2[3]);
            a3[0] = ffma2(hAB.x, w3, a3[0]); a3[1] = ffma2(hAB.y, w3, a3[1]);
            a3[2] = ffma2(hCD.x, w3, a3[2]); a3[3] = ffma2(hCD.y, w3, a3[3]);
        }

        // ---- in-warp kq-reduction: lane kq ends with row kq's 4 gates ----
        float pj[4][4];   // [gate][row]
        #pragma unroll
        for (int r = 0; r < 4; ++r) {
            pj[0][r] = hsum2(a0[r]);
            pj[1][r] = hsum2(a1[r]);
            pj[2][r] = hsum2(a2[r]);
            pj[3][r] = hsum2(a3[r]);
        }
        // round 1 (xor 1): full — lane holds sums over its kq pair
        #pragma unroll
        for (int j = 0; j < 4; ++j)
            #pragma unroll
            for (int r = 0; r < 4; ++r)
                pj[j][r] += __shfl_xor_sync(0xffffffffu, pj[j][r], 1);
        // round 2 (xor 2): pruned — keep rows with bit1 == p1, then pick bit0 == p0
        float gate[4];
        #pragma unroll
        for (int j = 0; j < 4; ++j) {
            float k0 = p1 ? pj[j][2] : pj[j][0];
            float k1 = p1 ? pj[j][3] : pj[j][1];
            float s0 = p1 ? pj[j][0] : pj[j][2];
            float s1 = p1 ? pj[j][1] : pj[j][3];
            k0 += __shfl_xor_sync(0xffffffffu, s0, 2);
            k1 += __shfl_xor_sync(0xffffffffu, s1, 2);
            gate[j] = p0 ? k1 : k0;
        }

        // ---- c/h update for (row kq, col g0) ----
        {
            float iv = gate[0] + cb0;
            float fv = gate[1] + cb1;
            float gv = gate[2] + cb2;
            float ov = gate[3] + cb3;
            float c = sigf(fv) * c_ + sigf(iv) * tanh_fast(gv);
            c_ = c;
            float h = sigf(ov) * tanh_fast(c);
            const int wbuf = (st & 1) ^ 1;
            hx_f[(((size_t)wbuf * K2T + (g0 >> 1)) * ROWS + kq) * 2 + (g0 & 1)] = h;
            if (tid < 128 && st + 1 < Tt)
                hx_f[(((size_t)wbuf * K2T + 64 + (xf >> 1)) * ROWS + xr) * 2 + (xf & 1)] = xnext;
        }
        __syncthreads();
    }

    // ---- FC head on final h (in buf 0 after 512 steps) ----
    if (tid < ROWS * Ll) {
        int r = tid / Ll, l = tid - r * Ll;
        float acc = b_fc[l];
        const float* wl = W_fc + l * Hh;
        #pragma unroll 16
        for (int k = 0; k < Hh; ++k)
            acc += reinterpret_cast<const float*>(&s->hx[0][k >> 1][r])[k & 1] * wl[k];
        out[(row0 + r) * Ll + l] = acc;
    }
}

// ---------------- host launch ----------------
extern "C" void kernel_launch(void* const* d_in, const int* in_sizes, int n_in,
                              void* d_out, int out_size) {
    const float* x    = (const float*)d_in[0];
    const float* W_ih = (const float*)d_in[1];
    const float* W_hh = (const float*)d_in[2];
    const float* b_ih = (const float*)d_in[3];
    const float* b_hh = (const float*)d_in[4];
    const float* W_fc = (const float*)d_in[5];
    const float* b_fc = (const float*)d_in[6];
    float* out = (float*)d_out;

    const size_t smem = sizeof(Smem);
    cudaFuncSetAttribute(lstm_kernel, cudaFuncAttributeMaxDynamicSharedMemorySize, (int)smem);
    lstm_kernel<<<Bb / ROWS, NTHREADS, smem>>>(x, W_ih, W_hh, b_ih, b_hh, W_fc, b_fc, out);
}